// round 14
// baseline (speedup 1.0000x reference)
#include <cuda_runtime.h>
#include <cuda_fp16.h>
#include <cstdint>

#define IN_F   4096
#define OUT_F  11008
#define GS     128
#define MROWS  8192

// x in fp16, k-permuted within each 8-group: order (j0,j4,j1,j5,j2,j6,j3,j7).
__device__ __half g_xh[(size_t)MROWS * IN_F];   // 67 MB scratch (device global)

// =============================== prepass ===================================
__global__ __launch_bounds__(256)
void conv_x_perm_kernel(const float* __restrict__ x)
{
    const size_t i = ((size_t)blockIdx.x * 256 + threadIdx.x) * 8;  // one 8-group
    const float4 a = *reinterpret_cast<const float4*>(&x[i]);
    const float4 b = *reinterpret_cast<const float4*>(&x[i + 4]);
    __half2 h0 = __floats2half2_rn(a.x, b.x);   // (j0, j4)
    __half2 h1 = __floats2half2_rn(a.y, b.y);   // (j1, j5)
    __half2 h2 = __floats2half2_rn(a.z, b.z);   // (j2, j6)
    __half2 h3 = __floats2half2_rn(a.w, b.w);   // (j3, j7)
    uint4 u;
    u.x = reinterpret_cast<uint32_t&>(h0);
    u.y = reinterpret_cast<uint32_t&>(h1);
    u.z = reinterpret_cast<uint32_t&>(h2);
    u.w = reinterpret_cast<uint32_t&>(h3);
    *reinterpret_cast<uint4*>(&g_xh[i]) = u;
}

// =============================== GEMM ======================================
constexpr int BM = 128;
constexpr int BN = 128;
constexpr int BK = 64;
constexpr int KPAD = 72;             // 144B row stride; odd quad count -> conflict-free
constexpr int THREADS = 192;         // 4 consumer warps + 2 producer warps
constexpr int NC = IN_F / BK;        // 64
constexpr int STAGES = 3;

constexpr int A_STG_B = BM * KPAD * 2;            // 18432
constexpr int B_STG_B = BN * KPAD * 2;            // 18432
constexpr int ST_B    = A_STG_B + B_STG_B;        // 36864
constexpr int STAGE_BASE = 1024;
constexpr int SMEM_TOTAL = STAGE_BASE + STAGES * ST_B;   // 111616  (x2 CTAs = 218 KB/SM)

__device__ __forceinline__ void mbar_init(uint32_t a, uint32_t cnt) {
    asm volatile("mbarrier.init.shared.b64 [%0], %1;" :: "r"(a), "r"(cnt) : "memory");
}
__device__ __forceinline__ void mbar_arrive(uint32_t a) {
    asm volatile("mbarrier.arrive.shared.b64 _, [%0];" :: "r"(a) : "memory");
}
__device__ __forceinline__ void mbar_wait(uint32_t a, uint32_t parity) {
    uint32_t done;
    asm volatile("{\n\t.reg .pred p;\n\t"
                 "mbarrier.try_wait.parity.acquire.cta.shared::cta.b64 p, [%1], %2;\n\t"
                 "selp.b32 %0, 1, 0, p;\n\t}"
                 : "=r"(done) : "r"(a), "r"(parity) : "memory");
    if (!done) {
        asm volatile("{\n\t.reg .pred P1;\n\t"
                     "WL_%=:\n\t"
                     "mbarrier.try_wait.parity.acquire.cta.shared::cta.b64 P1, [%0], %1, 0x989680;\n\t"
                     "@P1 bra.uni WD_%=;\n\t"
                     "bra.uni WL_%=;\n\t"
                     "WD_%=:\n\t}"
                     :: "r"(a), "r"(parity) : "memory");
    }
}

__device__ __forceinline__ void ldm_x4(uint32_t& r0, uint32_t& r1,
                                       uint32_t& r2, uint32_t& r3, uint32_t addr) {
    asm volatile("ldmatrix.sync.aligned.m8n8.x4.shared.b16 {%0,%1,%2,%3}, [%4];"
                 : "=r"(r0), "=r"(r1), "=r"(r2), "=r"(r3) : "r"(addr));
}

__device__ __forceinline__ void mma16816(float* d, const uint32_t* a, const uint32_t* b) {
    asm volatile("mma.sync.aligned.m16n8k16.row.col.f32.f16.f16.f32 "
                 "{%0,%1,%2,%3}, {%4,%5,%6,%7}, {%8,%9}, {%0,%1,%2,%3};"
                 : "+f"(d[0]), "+f"(d[1]), "+f"(d[2]), "+f"(d[3])
                 : "r"(a[0]), "r"(a[1]), "r"(a[2]), "r"(a[3]),
                   "r"(b[0]), "r"(b[1]));
}

__global__ __launch_bounds__(THREADS, 2)
void gptq_mma_kernel(const int*   __restrict__ qweight,
                     const int*   __restrict__ qzeros,
                     const float* __restrict__ scales,
                     float*       __restrict__ out)
{
    extern __shared__ __align__(16) char smem[];
    const uint32_t sb = (uint32_t)__cvta_generic_to_shared(smem);

    const int tid = threadIdx.x;
    const int lid = tid & 31;
    const int wid = tid >> 5;
    const int m0  = blockIdx.y * BM;
    const int n0  = blockIdx.x * BN;

    // mbarriers: full[s] at sb + s*16, empty[s] at sb + s*16 + 8
    if (tid == 0) {
        #pragma unroll
        for (int s = 0; s < STAGES; ++s) {
            mbar_init(sb + s * 16,     64);    // full: producer threads
            mbar_init(sb + s * 16 + 8, 128);   // empty: consumer threads
        }
    }
    __syncthreads();

    if (wid < 4) {
        // ====================== CONSUMER (warps 0-3) ======================
        const int wm = wid & 1;        // 2 warps along M (64 rows)
        const int wn = wid >> 1;       // 2 warps along N (64 cols)

        float acc[4][8][4];
        #pragma unroll
        for (int i = 0; i < 4; ++i)
            #pragma unroll
            for (int j = 0; j < 8; ++j)
                #pragma unroll
                for (int q = 0; q < 4; ++q) acc[i][j][q] = 0.0f;

        int st = 0, ph = 0;
        for (int kt = 0; kt < NC; ++kt) {
            mbar_wait(sb + st * 16, ph);                 // full[st]

            const uint32_t aS = sb + STAGE_BASE + st * ST_B;
            const uint32_t bS = aS + A_STG_B;
            #pragma unroll
            for (int ks = 0; ks < 4; ++ks) {
                uint32_t af[4][4];
                #pragma unroll
                for (int ma = 0; ma < 4; ++ma) {
                    const int row = wm * 64 + ma * 16 + (lid & 15);
                    const int col = ks * 16 + (lid >> 4) * 8;
                    ldm_x4(af[ma][0], af[ma][1], af[ma][2], af[ma][3],
                           aS + (uint32_t)(row * KPAD + col) * 2);
                }
                uint32_t bf[8][2];
                #pragma unroll
                for (int g4 = 0; g4 < 4; ++g4) {
                    const int row = wn * 64 + g4 * 16 + ((lid >> 4) & 1) * 8 + (lid & 7);
                    const int col = ks * 16 + ((lid >> 3) & 1) * 8;
                    uint32_t r0, r1, r2, r3;
                    ldm_x4(r0, r1, r2, r3, bS + (uint32_t)(row * KPAD + col) * 2);
                    bf[g4 * 2 + 0][0] = r0; bf[g4 * 2 + 0][1] = r1;
                    bf[g4 * 2 + 1][0] = r2; bf[g4 * 2 + 1][1] = r3;
                }
                // last smem read for this stage done -> release before final mma block
                if (ks == 3) mbar_arrive(sb + st * 16 + 8);   // empty[st]
                #pragma unroll
                for (int ma = 0; ma < 4; ++ma)
                    #pragma unroll
                    for (int na = 0; na < 8; ++na)
                        mma16816(acc[ma][na], af[ma], bf[na]);
            }

            if (++st == STAGES) { st = 0; ph ^= 1; }
        }

        // ---- epilogue ----
        #pragma unroll
        for (int ma = 0; ma < 4; ++ma) {
            const int row = m0 + wm * 64 + ma * 16 + (lid >> 2);
            #pragma unroll
            for (int na = 0; na < 8; ++na) {
                const int col = n0 + wn * 64 + na * 8 + (lid & 3) * 2;
                float2 v01, v23;
                v01.x = acc[ma][na][0]; v01.y = acc[ma][na][1];
                v23.x = acc[ma][na][2]; v23.y = acc[ma][na][3];
                *reinterpret_cast<float2*>(&out[(size_t)row * OUT_F + col]) = v01;
                *reinterpret_cast<float2*>(&out[(size_t)(row + 8) * OUT_F + col]) = v23;
            }
        }
    } else {
        // ====================== PRODUCER (warps 4-5) ======================
        const int ptid = tid - 128;    // 0..63
        const int zsh  = (ptid & 7) * 4;

        // W prefetch double-buffer (A streamed inside storeP; 2nd CTA covers latency)
        int   wq[2][2][8];
        int   zv[2][2];
        float sv[2][2];

        auto loadW = [&](int kt, int buf) {
            const int k0 = kt * BK;
            const int g  = kt >> 1;    // k0 / GS
            #pragma unroll
            for (int c = 0; c < 2; ++c) {
                const int ncol = n0 + ptid + 64 * c;
                zv[buf][c] = qzeros[(size_t)g * (OUT_F / 8) + (ncol >> 3)];
                sv[buf][c] = scales[(size_t)g * OUT_F + ncol];
                #pragma unroll
                for (int p = 0; p < 8; ++p)
                    wq[buf][c][p] = qweight[(size_t)(k0 / 8 + p) * OUT_F + ncol];
            }
        };

        auto storeP = [&](int kt, int st, int buf) {
            const int k0 = kt * BK;
            char* aP = smem + STAGE_BASE + st * ST_B;
            char* bP = aP + A_STG_B;

            // ---- A: 128 rows x 8 segs = 1024 uint4, 16/thread in 2 batches ----
            #pragma unroll
            for (int h = 0; h < 2; ++h) {
                uint4 v[8];
                #pragma unroll
                for (int i = 0; i < 8; ++i) {
                    const int task = (h * 8 + i) * 64 + ptid;
                    const int row = task >> 3, seg = task & 7;
                    v[i] = *reinterpret_cast<const uint4*>(
                        &g_xh[(size_t)(m0 + row) * IN_F + k0 + seg * 8]);
                }
                #pragma unroll
                for (int i = 0; i < 8; ++i) {
                    const int task = (h * 8 + i) * 64 + ptid;
                    const int row = task >> 3, seg = task & 7;
                    *reinterpret_cast<uint4*>(aP + (row * KPAD + seg * 8) * 2) = v[i];
                }
            }

            // ---- B: dequant 2 cols x 8 packed rows from prefetched regs ----
            #pragma unroll
            for (int c = 0; c < 2; ++c) {
                const float zf = (float)(((zv[buf][c] >> zsh) & 0xF) + 1 + 1024);
                const __half2 z2 = __floats2half2_rn(zf, zf);
                const __half2 s2 = __floats2half2_rn(sv[buf][c], sv[buf][c]);
                const int colo = ptid + 64 * c;
                #pragma unroll
                for (int p = 0; p < 8; ++p) {
                    const uint32_t q = (uint32_t)wq[buf][c][p];
                    uint4 u;
                    uint32_t t;
                    __half2 hv, r;
                    t = (q & 0x000F000Fu) | 0x64006400u;
                    hv = reinterpret_cast<__half2&>(t);
                    r = __hmul2(__hsub2(hv, z2), s2);  u.x = reinterpret_cast<uint32_t&>(r);
                    t = ((q >> 4) & 0x000F000Fu) | 0x64006400u;
                    hv = reinterpret_cast<__half2&>(t);
                    r = __hmul2(__hsub2(hv, z2), s2);  u.y = reinterpret_cast<uint32_t&>(r);
                    t = ((q >> 8) & 0x000F000Fu) | 0x64006400u;
                    hv = reinterpret_cast<__half2&>(t);
                    r = __hmul2(__hsub2(hv, z2), s2);  u.z = reinterpret_cast<uint32_t&>(r);
                    t = ((q >> 12) & 0x000F000Fu) | 0x64006400u;
                    hv = reinterpret_cast<__half2&>(t);
                    r = __hmul2(__hsub2(hv, z2), s2);  u.w = reinterpret_cast<uint32_t&>(r);
                    *reinterpret_cast<uint4*>(bP + (colo * KPAD + p * 8) * 2) = u;
                }
            }
        };

        loadW(0, 0);
        int st = 0, ph = 1;            // empty-wait passes for the first STAGES chunks

        #pragma unroll 1
        for (int kt = 0; kt < NC; kt += 2) {
            if (kt + 1 < NC) loadW(kt + 1, 1);
            mbar_wait(sb + st * 16 + 8, ph);             // empty[st]
            storeP(kt, st, 0);
            mbar_arrive(sb + st * 16);                   // full[st]
            if (++st == STAGES) { st = 0; ph ^= 1; }

            if (kt + 2 < NC) loadW(kt + 2, 0);
            mbar_wait(sb + st * 16 + 8, ph);             // empty[st]
            storeP(kt + 1, st, 1);
            mbar_arrive(sb + st * 16);                   // full[st]
            if (++st == STAGES) { st = 0; ph ^= 1; }
        }
    }
}

// =============================== launch ====================================
extern "C" void kernel_launch(void* const* d_in, const int* in_sizes, int n_in,
                              void* d_out, int out_size)
{
    const float* x       = (const float*)d_in[0];
    const int*   qweight = (const int*)  d_in[1];
    const int*   qzeros  = (const int*)  d_in[2];
    const float* scales  = (const float*)d_in[3];
    float*       out     = (float*)d_out;

    cudaFuncSetAttribute(gptq_mma_kernel,
                         cudaFuncAttributeMaxDynamicSharedMemorySize, SMEM_TOTAL);

    conv_x_perm_kernel<<<(MROWS * IN_F) / (256 * 8), 256>>>(x);

    dim3 grid(OUT_F / BN, MROWS / BM);   // 86 x 64
    gptq_mma_kernel<<<grid, THREADS, SMEM_TOTAL>>>(qweight, qzeros, scales, out);
}

// round 15
// speedup vs baseline: 1.4201x; 1.4201x over previous
#include <cuda_runtime.h>
#include <cuda_fp16.h>
#include <cstdint>

#define IN_F   4096
#define OUT_F  11008
#define GS     128
#define MROWS  8192

// x in fp16, k-permuted within each 8-group: order (j0,j4,j1,j5,j2,j6,j3,j7).
__device__ __half g_xh[(size_t)MROWS * IN_F];   // 67 MB scratch (device global)

// =============================== prepass ===================================
__global__ __launch_bounds__(256)
void conv_x_perm_kernel(const float* __restrict__ x)
{
    const size_t i = ((size_t)blockIdx.x * 256 + threadIdx.x) * 8;  // one 8-group
    const float4 a = *reinterpret_cast<const float4*>(&x[i]);
    const float4 b = *reinterpret_cast<const float4*>(&x[i + 4]);
    __half2 h0 = __floats2half2_rn(a.x, b.x);   // (j0, j4)
    __half2 h1 = __floats2half2_rn(a.y, b.y);   // (j1, j5)
    __half2 h2 = __floats2half2_rn(a.z, b.z);   // (j2, j6)
    __half2 h3 = __floats2half2_rn(a.w, b.w);   // (j3, j7)
    uint4 u;
    u.x = reinterpret_cast<uint32_t&>(h0);
    u.y = reinterpret_cast<uint32_t&>(h1);
    u.z = reinterpret_cast<uint32_t&>(h2);
    u.w = reinterpret_cast<uint32_t&>(h3);
    *reinterpret_cast<uint4*>(&g_xh[i]) = u;
}

// =============================== GEMM ======================================
constexpr int BM = 128;
constexpr int BN = 256;
constexpr int BK = 64;
constexpr int KPAD = 72;             // 144B row stride; odd quad count -> conflict-free
constexpr int THREADS = 384;         // 8 consumer warps + 4 producer warps
constexpr int NC = IN_F / BK;        // 64
constexpr int STAGES = 3;

constexpr int A_STG_B = BM * KPAD * 2;            // 18432
constexpr int B_STG_B = BN * KPAD * 2;            // 36864
constexpr int ST_B    = A_STG_B + B_STG_B;        // 55296
constexpr int STAGE_BASE = 1024;
constexpr int SMEM_TOTAL = STAGE_BASE + STAGES * ST_B;   // 166912

__device__ __forceinline__ void mbar_init(uint32_t a, uint32_t cnt) {
    asm volatile("mbarrier.init.shared.b64 [%0], %1;" :: "r"(a), "r"(cnt) : "memory");
}
__device__ __forceinline__ void mbar_arrive(uint32_t a) {
    asm volatile("mbarrier.arrive.shared.b64 _, [%0];" :: "r"(a) : "memory");
}
__device__ __forceinline__ void mbar_wait(uint32_t a, uint32_t parity) {
    uint32_t done;
    asm volatile("{\n\t.reg .pred p;\n\t"
                 "mbarrier.try_wait.parity.acquire.cta.shared::cta.b64 p, [%1], %2;\n\t"
                 "selp.b32 %0, 1, 0, p;\n\t}"
                 : "=r"(done) : "r"(a), "r"(parity) : "memory");
    if (!done) {
        asm volatile("{\n\t.reg .pred P1;\n\t"
                     "WL_%=:\n\t"
                     "mbarrier.try_wait.parity.acquire.cta.shared::cta.b64 P1, [%0], %1, 0x989680;\n\t"
                     "@P1 bra.uni WD_%=;\n\t"
                     "bra.uni WL_%=;\n\t"
                     "WD_%=:\n\t}"
                     :: "r"(a), "r"(parity) : "memory");
    }
}

__device__ __forceinline__ void ldm_x4(uint32_t& r0, uint32_t& r1,
                                       uint32_t& r2, uint32_t& r3, uint32_t addr) {
    asm volatile("ldmatrix.sync.aligned.m8n8.x4.shared.b16 {%0,%1,%2,%3}, [%4];"
                 : "=r"(r0), "=r"(r1), "=r"(r2), "=r"(r3) : "r"(addr));
}

__device__ __forceinline__ void mma16816(float* d, const uint32_t* a, const uint32_t* b) {
    asm volatile("mma.sync.aligned.m16n8k16.row.col.f32.f16.f16.f32 "
                 "{%0,%1,%2,%3}, {%4,%5,%6,%7}, {%8,%9}, {%0,%1,%2,%3};"
                 : "+f"(d[0]), "+f"(d[1]), "+f"(d[2]), "+f"(d[3])
                 : "r"(a[0]), "r"(a[1]), "r"(a[2]), "r"(a[3]),
                   "r"(b[0]), "r"(b[1]));
}

__global__ __launch_bounds__(THREADS, 1)
void gptq_mma_kernel(const int*   __restrict__ qweight,
                     const int*   __restrict__ qzeros,
                     const float* __restrict__ scales,
                     float*       __restrict__ out)
{
    extern __shared__ __align__(16) char smem[];
    const uint32_t sb = (uint32_t)__cvta_generic_to_shared(smem);

    const int tid = threadIdx.x;
    const int lid = tid & 31;
    const int wid = tid >> 5;
    const int m0  = blockIdx.y * BM;
    const int n0  = blockIdx.x * BN;

    // mbarriers: full[s] at sb + s*16, empty[s] at sb + s*16 + 8
    if (tid == 0) {
        #pragma unroll
        for (int s = 0; s < STAGES; ++s) {
            mbar_init(sb + s * 16,     128);   // full: producer threads
            mbar_init(sb + s * 16 + 8, 256);   // empty: consumer threads
        }
    }
    __syncthreads();

    if (wid < 8) {
        // ====================== CONSUMER ======================
        const int wm = wid & 1;        // 2 warps along M (64 rows)
        const int wn = wid >> 1;       // 4 warps along N (64 cols)

        float acc[4][8][4];
        #pragma unroll
        for (int i = 0; i < 4; ++i)
            #pragma unroll
            for (int j = 0; j < 8; ++j)
                #pragma unroll
                for (int q = 0; q < 4; ++q) acc[i][j][q] = 0.0f;

        int st = 0, ph = 0;
        mbar_wait(sb + 0 * 16, 0);                       // full[0]
        for (int kt = 0; kt < NC; ++kt) {
            const uint32_t aS = sb + STAGE_BASE + st * ST_B;
            const uint32_t bS = aS + A_STG_B;
            #pragma unroll
            for (int ks = 0; ks < 4; ++ks) {
                uint32_t af[4][4];
                #pragma unroll
                for (int ma = 0; ma < 4; ++ma) {
                    const int row = wm * 64 + ma * 16 + (lid & 15);
                    const int col = ks * 16 + (lid >> 4) * 8;
                    ldm_x4(af[ma][0], af[ma][1], af[ma][2], af[ma][3],
                           aS + (uint32_t)(row * KPAD + col) * 2);
                }
                uint32_t bf[8][2];
                #pragma unroll
                for (int g4 = 0; g4 < 4; ++g4) {
                    const int row = wn * 64 + g4 * 16 + ((lid >> 4) & 1) * 8 + (lid & 7);
                    const int col = ks * 16 + ((lid >> 3) & 1) * 8;
                    uint32_t r0, r1, r2, r3;
                    ldm_x4(r0, r1, r2, r3, bS + (uint32_t)(row * KPAD + col) * 2);
                    bf[g4 * 2 + 0][0] = r0; bf[g4 * 2 + 0][1] = r1;
                    bf[g4 * 2 + 1][0] = r2; bf[g4 * 2 + 1][1] = r3;
                }
                if (ks == 3) {
                    // all smem reads done: release stage, then pre-wait on the
                    // NEXT stage *before* the final mma burst so the deferred
                    // 32 HMMAs cover the wait-return + next-chunk ldm latency.
                    mbar_arrive(sb + st * 16 + 8);       // empty[st]
                    const int nst = (st + 1 == STAGES) ? 0 : st + 1;
                    const int nph = (st + 1 == STAGES) ? (ph ^ 1) : ph;
                    if (kt + 1 < NC)
                        mbar_wait(sb + nst * 16, nph);   // full[next]
                    st = nst; ph = nph;
                }
                #pragma unroll
                for (int ma = 0; ma < 4; ++ma)
                    #pragma unroll
                    for (int na = 0; na < 8; ++na)
                        mma16816(acc[ma][na], af[ma], bf[na]);
            }
        }

        // ---- epilogue ----
        #pragma unroll
        for (int ma = 0; ma < 4; ++ma) {
            const int row = m0 + wm * 64 + ma * 16 + (lid >> 2);
            #pragma unroll
            for (int na = 0; na < 8; ++na) {
                const int col = n0 + wn * 64 + na * 8 + (lid & 3) * 2;
                float2 v01, v23;
                v01.x = acc[ma][na][0]; v01.y = acc[ma][na][1];
                v23.x = acc[ma][na][2]; v23.y = acc[ma][na][3];
                *reinterpret_cast<float2*>(&out[(size_t)row * OUT_F + col]) = v01;
                *reinterpret_cast<float2*>(&out[(size_t)(row + 8) * OUT_F + col]) = v23;
            }
        }
    } else {
        // ====================== PRODUCER (warps 8-11) ======================
        const int ptid = tid - 256;    // 0..127
        const int zsh  = (ptid & 7) * 4;

        // double-buffered prefetch registers (literal indices after unroll)
        uint4 xr[2][8];
        int   wq[2][2][8];
        int   zv[2][2];
        float sv[2][2];

        auto loadP = [&](int kt, int buf) {
            const int k0 = kt * BK;
            const int g  = kt >> 1;    // k0 / GS
            #pragma unroll
            for (int i = 0; i < 8; ++i) {
                const int task = i * 128 + ptid;
                const int row = task >> 3, seg = task & 7;
                xr[buf][i] = *reinterpret_cast<const uint4*>(
                    &g_xh[(size_t)(m0 + row) * IN_F + k0 + seg * 8]);
            }
            #pragma unroll
            for (int c = 0; c < 2; ++c) {
                const int ncol = n0 + ptid + 128 * c;
                zv[buf][c] = qzeros[(size_t)g * (OUT_F / 8) + (ncol >> 3)];
                sv[buf][c] = scales[(size_t)g * OUT_F + ncol];
                #pragma unroll
                for (int p = 0; p < 8; ++p)
                    wq[buf][c][p] = qweight[(size_t)(k0 / 8 + p) * OUT_F + ncol];
            }
        };

        auto storeP = [&](int st, int buf) {
            char* aP = smem + STAGE_BASE + st * ST_B;
            char* bP = aP + A_STG_B;
            #pragma unroll
            for (int i = 0; i < 8; ++i) {
                const int task = i * 128 + ptid;
                const int row = task >> 3, seg = task & 7;
                *reinterpret_cast<uint4*>(aP + (row * KPAD + seg * 8) * 2) = xr[buf][i];
            }
            #pragma unroll
            for (int c = 0; c < 2; ++c) {
                const float zf = (float)(((zv[buf][c] >> zsh) & 0xF) + 1 + 1024);
                const __half2 z2 = __floats2half2_rn(zf, zf);
                const __half2 s2 = __floats2half2_rn(sv[buf][c], sv[buf][c]);
                const int colo = ptid + 128 * c;
                #pragma unroll
                for (int p = 0; p < 8; ++p) {
                    const uint32_t q = (uint32_t)wq[buf][c][p];
                    uint4 u;
                    uint32_t t;
                    __half2 hv, r;
                    t = (q & 0x000F000Fu) | 0x64006400u;
                    hv = reinterpret_cast<__half2&>(t);
                    r = __hmul2(__hsub2(hv, z2), s2);  u.x = reinterpret_cast<uint32_t&>(r);
                    t = ((q >> 4) & 0x000F000Fu) | 0x64006400u;
                    hv = reinterpret_cast<__half2&>(t);
                    r = __hmul2(__hsub2(hv, z2), s2);  u.y = reinterpret_cast<uint32_t&>(r);
                    t = ((q >> 8) & 0x000F000Fu) | 0x64006400u;
                    hv = reinterpret_cast<__half2&>(t);
                    r = __hmul2(__hsub2(hv, z2), s2);  u.z = reinterpret_cast<uint32_t&>(r);
                    t = ((q >> 12) & 0x000F000Fu) | 0x64006400u;
                    hv = reinterpret_cast<__half2&>(t);
                    r = __hmul2(__hsub2(hv, z2), s2);  u.w = reinterpret_cast<uint32_t&>(r);
                    *reinterpret_cast<uint4*>(bP + (colo * KPAD + p * 8) * 2) = u;
                }
            }
        };

        loadP(0, 0);
        int st = 0, ph = 1;            // empty-wait passes for the first STAGES chunks

        #pragma unroll 1
        for (int kt = 0; kt < NC; kt += 2) {
            // even chunk: store buf0, prefetch kt+1 into buf1 first
            if (kt + 1 < NC) loadP(kt + 1, 1);
            mbar_wait(sb + st * 16 + 8, ph);             // empty[st]
            storeP(st, 0);
            mbar_arrive(sb + st * 16);                   // full[st]
            if (++st == STAGES) { st = 0; ph ^= 1; }

            // odd chunk: store buf1, prefetch kt+2 into buf0 first
            if (kt + 2 < NC) loadP(kt + 2, 0);
            mbar_wait(sb + st * 16 + 8, ph);             // empty[st]
            storeP(st, 1);
            mbar_arrive(sb + st * 16);                   // full[st]
            if (++st == STAGES) { st = 0; ph ^= 1; }
        }
    }
}

// =============================== launch ====================================
extern "C" void kernel_launch(void* const* d_in, const int* in_sizes, int n_in,
                              void* d_out, int out_size)
{
    const float* x       = (const float*)d_in[0];
    const int*   qweight = (const int*)  d_in[1];
    const int*   qzeros  = (const int*)  d_in[2];
    const float* scales  = (const float*)d_in[3];
    float*       out     = (float*)d_out;

    cudaFuncSetAttribute(gptq_mma_kernel,
                         cudaFuncAttributeMaxDynamicSharedMemorySize, SMEM_TOTAL);

    conv_x_perm_kernel<<<(MROWS * IN_F) / (256 * 8), 256>>>(x);

    dim3 grid(OUT_F / BN, MROWS / BM);   // 43 x 64
    gptq_mma_kernel<<<grid, THREADS, SMEM_TOTAL>>>(qweight, qzeros, scales, out);
}

// round 16
// speedup vs baseline: 1.6153x; 1.1375x over previous
#include <cuda_runtime.h>
#include <cuda_fp16.h>
#include <cstdint>

#define IN_F   4096
#define OUT_F  11008
#define GS     128
#define MROWS  8192

// x in fp16, k-permuted within each 8-group: order (j0,j4,j1,j5,j2,j6,j3,j7).
__device__ __half g_xh[(size_t)MROWS * IN_F];   // 67 MB scratch (device global)

// =============================== prepass ===================================
__global__ __launch_bounds__(256)
void conv_x_perm_kernel(const float* __restrict__ x)
{
    const size_t i = ((size_t)blockIdx.x * 256 + threadIdx.x) * 8;  // one 8-group
    const float4 a = *reinterpret_cast<const float4*>(&x[i]);
    const float4 b = *reinterpret_cast<const float4*>(&x[i + 4]);
    __half2 h0 = __floats2half2_rn(a.x, b.x);   // (j0, j4)
    __half2 h1 = __floats2half2_rn(a.y, b.y);   // (j1, j5)
    __half2 h2 = __floats2half2_rn(a.z, b.z);   // (j2, j6)
    __half2 h3 = __floats2half2_rn(a.w, b.w);   // (j3, j7)
    uint4 u;
    u.x = reinterpret_cast<uint32_t&>(h0);
    u.y = reinterpret_cast<uint32_t&>(h1);
    u.z = reinterpret_cast<uint32_t&>(h2);
    u.w = reinterpret_cast<uint32_t&>(h3);
    *reinterpret_cast<uint4*>(&g_xh[i]) = u;
}

// =============================== GEMM ======================================
constexpr int BM = 128;
constexpr int BN = 256;
constexpr int BK = 64;
constexpr int KPAD = 72;             // 144B row stride; odd quad count -> conflict-free
constexpr int THREADS = 384;         // 8 consumer warps + 4 producer warps
constexpr int NC = IN_F / BK;        // 64
constexpr int STAGES = 4;            // deeper ring: absorb producer jitter

constexpr int A_STG_B = BM * KPAD * 2;            // 18432
constexpr int B_STG_B = BN * KPAD * 2;            // 36864
constexpr int ST_B    = A_STG_B + B_STG_B;        // 55296
constexpr int STAGE_BASE = 1024;
constexpr int SMEM_TOTAL = STAGE_BASE + STAGES * ST_B;   // 222208 (< 227 KB)

__device__ __forceinline__ void mbar_init(uint32_t a, uint32_t cnt) {
    asm volatile("mbarrier.init.shared.b64 [%0], %1;" :: "r"(a), "r"(cnt) : "memory");
}
__device__ __forceinline__ void mbar_arrive(uint32_t a) {
    asm volatile("mbarrier.arrive.shared.b64 _, [%0];" :: "r"(a) : "memory");
}
__device__ __forceinline__ void mbar_wait(uint32_t a, uint32_t parity) {
    uint32_t done;
    asm volatile("{\n\t.reg .pred p;\n\t"
                 "mbarrier.try_wait.parity.acquire.cta.shared::cta.b64 p, [%1], %2;\n\t"
                 "selp.b32 %0, 1, 0, p;\n\t}"
                 : "=r"(done) : "r"(a), "r"(parity) : "memory");
    if (!done) {
        asm volatile("{\n\t.reg .pred P1;\n\t"
                     "WL_%=:\n\t"
                     "mbarrier.try_wait.parity.acquire.cta.shared::cta.b64 P1, [%0], %1, 0x989680;\n\t"
                     "@P1 bra.uni WD_%=;\n\t"
                     "bra.uni WL_%=;\n\t"
                     "WD_%=:\n\t}"
                     :: "r"(a), "r"(parity) : "memory");
    }
}

__device__ __forceinline__ void ldm_x4(uint32_t& r0, uint32_t& r1,
                                       uint32_t& r2, uint32_t& r3, uint32_t addr) {
    asm volatile("ldmatrix.sync.aligned.m8n8.x4.shared.b16 {%0,%1,%2,%3}, [%4];"
                 : "=r"(r0), "=r"(r1), "=r"(r2), "=r"(r3) : "r"(addr));
}

__device__ __forceinline__ void mma16816(float* d, const uint32_t* a, const uint32_t* b) {
    asm volatile("mma.sync.aligned.m16n8k16.row.col.f32.f16.f16.f32 "
                 "{%0,%1,%2,%3}, {%4,%5,%6,%7}, {%8,%9}, {%0,%1,%2,%3};"
                 : "+f"(d[0]), "+f"(d[1]), "+f"(d[2]), "+f"(d[3])
                 : "r"(a[0]), "r"(a[1]), "r"(a[2]), "r"(a[3]),
                   "r"(b[0]), "r"(b[1]));
}

__global__ __launch_bounds__(THREADS, 1)
void gptq_mma_kernel(const int*   __restrict__ qweight,
                     const int*   __restrict__ qzeros,
                     const float* __restrict__ scales,
                     float*       __restrict__ out)
{
    extern __shared__ __align__(16) char smem[];
    const uint32_t sb = (uint32_t)__cvta_generic_to_shared(smem);

    const int tid = threadIdx.x;
    const int lid = tid & 31;
    const int wid = tid >> 5;
    const int m0  = blockIdx.y * BM;
    const int n0  = blockIdx.x * BN;

    // mbarriers: full[s] at sb + s*16, empty[s] at sb + s*16 + 8
    if (tid == 0) {
        #pragma unroll
        for (int s = 0; s < STAGES; ++s) {
            mbar_init(sb + s * 16,     128);   // full: producer threads
            mbar_init(sb + s * 16 + 8, 256);   // empty: consumer threads
        }
    }
    __syncthreads();

    if (wid < 8) {
        // ====================== CONSUMER ======================
        const int wm = wid & 1;        // 2 warps along M (64 rows)
        const int wn = wid >> 1;       // 4 warps along N (64 cols)

        float acc[4][8][4];
        #pragma unroll
        for (int i = 0; i < 4; ++i)
            #pragma unroll
            for (int j = 0; j < 8; ++j)
                #pragma unroll
                for (int q = 0; q < 4; ++q) acc[i][j][q] = 0.0f;

        int st = 0, ph = 0;
        for (int kt = 0; kt < NC; ++kt) {
            mbar_wait(sb + st * 16, ph);                 // full[st]

            const uint32_t aS = sb + STAGE_BASE + st * ST_B;
            const uint32_t bS = aS + A_STG_B;
            #pragma unroll
            for (int ks = 0; ks < 4; ++ks) {
                uint32_t af[4][4];
                #pragma unroll
                for (int ma = 0; ma < 4; ++ma) {
                    const int row = wm * 64 + ma * 16 + (lid & 15);
                    const int col = ks * 16 + (lid >> 4) * 8;
                    ldm_x4(af[ma][0], af[ma][1], af[ma][2], af[ma][3],
                           aS + (uint32_t)(row * KPAD + col) * 2);
                }
                uint32_t bf[8][2];
                #pragma unroll
                for (int g4 = 0; g4 < 4; ++g4) {
                    const int row = wn * 64 + g4 * 16 + ((lid >> 4) & 1) * 8 + (lid & 7);
                    const int col = ks * 16 + ((lid >> 3) & 1) * 8;
                    uint32_t r0, r1, r2, r3;
                    ldm_x4(r0, r1, r2, r3, bS + (uint32_t)(row * KPAD + col) * 2);
                    bf[g4 * 2 + 0][0] = r0; bf[g4 * 2 + 0][1] = r1;
                    bf[g4 * 2 + 1][0] = r2; bf[g4 * 2 + 1][1] = r3;
                }
                // all smem reads for this stage are done after the last ldm:
                // release the stage before the final mma block.
                if (ks == 3) mbar_arrive(sb + st * 16 + 8);   // empty[st]
                #pragma unroll
                for (int ma = 0; ma < 4; ++ma)
                    #pragma unroll
                    for (int na = 0; na < 8; ++na)
                        mma16816(acc[ma][na], af[ma], bf[na]);
            }

            if (++st == STAGES) { st = 0; ph ^= 1; }
        }

        // ---- epilogue ----
        #pragma unroll
        for (int ma = 0; ma < 4; ++ma) {
            const int row = m0 + wm * 64 + ma * 16 + (lid >> 2);
            #pragma unroll
            for (int na = 0; na < 8; ++na) {
                const int col = n0 + wn * 64 + na * 8 + (lid & 3) * 2;
                float2 v01, v23;
                v01.x = acc[ma][na][0]; v01.y = acc[ma][na][1];
                v23.x = acc[ma][na][2]; v23.y = acc[ma][na][3];
                *reinterpret_cast<float2*>(&out[(size_t)row * OUT_F + col]) = v01;
                *reinterpret_cast<float2*>(&out[(size_t)(row + 8) * OUT_F + col]) = v23;
            }
        }
    } else {
        // ====================== PRODUCER (warps 8-11) ======================
        const int ptid = tid - 256;    // 0..127
        const int zsh  = (ptid & 7) * 4;

        // double-buffered prefetch registers (literal indices after unroll)
        uint4 xr[2][8];
        int   wq[2][2][8];
        int   zv[2][2];
        float sv[2][2];

        auto loadP = [&](int kt, int buf) {
            const int k0 = kt * BK;
            const int g  = kt >> 1;    // k0 / GS
            #pragma unroll
            for (int i = 0; i < 8; ++i) {
                const int task = i * 128 + ptid;
                const int row = task >> 3, seg = task & 7;
                xr[buf][i] = *reinterpret_cast<const uint4*>(
                    &g_xh[(size_t)(m0 + row) * IN_F + k0 + seg * 8]);
            }
            #pragma unroll
            for (int c = 0; c < 2; ++c) {
                const int ncol = n0 + ptid + 128 * c;
                zv[buf][c] = qzeros[(size_t)g * (OUT_F / 8) + (ncol >> 3)];
                sv[buf][c] = scales[(size_t)g * OUT_F + ncol];
                #pragma unroll
                for (int p = 0; p < 8; ++p)
                    wq[buf][c][p] = qweight[(size_t)(k0 / 8 + p) * OUT_F + ncol];
            }
        };

        auto storeP = [&](int st, int buf) {
            char* aP = smem + STAGE_BASE + st * ST_B;
            char* bP = aP + A_STG_B;
            #pragma unroll
            for (int i = 0; i < 8; ++i) {
                const int task = i * 128 + ptid;
                const int row = task >> 3, seg = task & 7;
                *reinterpret_cast<uint4*>(aP + (row * KPAD + seg * 8) * 2) = xr[buf][i];
            }
            #pragma unroll
            for (int c = 0; c < 2; ++c) {
                const float zf = (float)(((zv[buf][c] >> zsh) & 0xF) + 1 + 1024);
                const __half2 z2 = __floats2half2_rn(zf, zf);
                const __half2 s2 = __floats2half2_rn(sv[buf][c], sv[buf][c]);
                const int colo = ptid + 128 * c;
                #pragma unroll
                for (int p = 0; p < 8; ++p) {
                    const uint32_t q = (uint32_t)wq[buf][c][p];
                    uint4 u;
                    uint32_t t;
                    __half2 hv, r;
                    t = (q & 0x000F000Fu) | 0x64006400u;
                    hv = reinterpret_cast<__half2&>(t);
                    r = __hmul2(__hsub2(hv, z2), s2);  u.x = reinterpret_cast<uint32_t&>(r);
                    t = ((q >> 4) & 0x000F000Fu) | 0x64006400u;
                    hv = reinterpret_cast<__half2&>(t);
                    r = __hmul2(__hsub2(hv, z2), s2);  u.y = reinterpret_cast<uint32_t&>(r);
                    t = ((q >> 8) & 0x000F000Fu) | 0x64006400u;
                    hv = reinterpret_cast<__half2&>(t);
                    r = __hmul2(__hsub2(hv, z2), s2);  u.z = reinterpret_cast<uint32_t&>(r);
                    t = ((q >> 12) & 0x000F000Fu) | 0x64006400u;
                    hv = reinterpret_cast<__half2&>(t);
                    r = __hmul2(__hsub2(hv, z2), s2);  u.w = reinterpret_cast<uint32_t&>(r);
                    *reinterpret_cast<uint4*>(bP + (colo * KPAD + p * 8) * 2) = u;
                }
            }
        };

        loadP(0, 0);
        int st = 0, ph = 1;            // empty-wait passes for the first STAGES chunks

        #pragma unroll 1
        for (int kt = 0; kt < NC; kt += 2) {
            // even chunk: store buf0, prefetch kt+1 into buf1 first
            if (kt + 1 < NC) loadP(kt + 1, 1);
            mbar_wait(sb + st * 16 + 8, ph);             // empty[st]
            storeP(st, 0);
            mbar_arrive(sb + st * 16);                   // full[st]
            if (++st == STAGES) { st = 0; ph ^= 1; }

            // odd chunk: store buf1, prefetch kt+2 into buf0 first
            if (kt + 2 < NC) loadP(kt + 2, 0);
            mbar_wait(sb + st * 16 + 8, ph);             // empty[st]
            storeP(st, 1);
            mbar_arrive(sb + st * 16);                   // full[st]
            if (++st == STAGES) { st = 0; ph ^= 1; }
        }
    }
}

// =============================== launch ====================================
extern "C" void kernel_launch(void* const* d_in, const int* in_sizes, int n_in,
                              void* d_out, int out_size)
{
    const float* x       = (const float*)d_in[0];
    const int*   qweight = (const int*)  d_in[1];
    const int*   qzeros  = (const int*)  d_in[2];
    const float* scales  = (const float*)d_in[3];
    float*       out     = (float*)d_out;

    cudaFuncSetAttribute(gptq_mma_kernel,
                         cudaFuncAttributeMaxDynamicSharedMemorySize, SMEM_TOTAL);

    conv_x_perm_kernel<<<(MROWS * IN_F) / (256 * 8), 256>>>(x);

    dim3 grid(OUT_F / BN, MROWS / BM);   // 43 x 64
    gptq_mma_kernel<<<grid, THREADS, SMEM_TOTAL>>>(qweight, qzeros, scales, out);
}